// round 1
// baseline (speedup 1.0000x reference)
#include <cuda_runtime.h>
#include <cuda_bf16.h>
#include <cstdint>

// Problem constants
#define B_SZ   2048
#define L_SZ   200000
#define H_SZ   64

// Tiling
#define BM 128          // batch rows per block
#define BN 256          // label columns per block (== threads)
#define GX ((L_SZ + BN - 1) / BN)   // 782 column blocks
#define GY (B_SZ / BM)              // 16  row blocks

// Deterministic partial sums of exp(logit) per (row, column-block)
__device__ float g_partial[B_SZ * GX];
__device__ float g_rowsum[B_SZ];

// ---------------------------------------------------------------------------
// Kernel 1: gather return_embed into the output tail region.
// out_embed is only 4B-aligned (odd float offset), so scalar stores.
// ---------------------------------------------------------------------------
__global__ void prep_kernel(const int* __restrict__ label,
                            const float* __restrict__ table,
                            float* __restrict__ out_embed) {
    int i = blockIdx.x * blockDim.x + threadIdx.x;
    if (i < B_SZ) {
        int lab = label[i];
        const float* src = table + (size_t)lab * H_SZ;
        float* dst = out_embed + (size_t)i * H_SZ;
        #pragma unroll
        for (int k = 0; k < H_SZ; k++) dst[k] = src[k];
    }
}

// ---------------------------------------------------------------------------
// Kernel 2: logits = sigmoid(embed @ W^T + b), plus per-block exp partials.
// One thread per output column n; BM=128 rows per block via smem embed tile.
// ---------------------------------------------------------------------------
__global__ __launch_bounds__(BN)
void logits_kernel(const int* __restrict__ label,
                   const float* __restrict__ table,
                   const float* __restrict__ W,
                   const float* __restrict__ b,
                   float* __restrict__ out) {
    __shared__ float s_emb[BM][H_SZ];        // 32 KB
    __shared__ float s_warp[BM][8];          // per-warp exp partials, 4 KB

    const int m0 = blockIdx.y * BM;
    const int n  = blockIdx.x * BN + threadIdx.x;
    const bool valid = (n < L_SZ);
    const int wid = threadIdx.x >> 5;

    // Cooperative gather of the embed tile: table[label[m0+m]][:]
    for (int idx = threadIdx.x; idx < BM * (H_SZ / 4); idx += BN) {
        int m  = idx >> 4;          // H/4 = 16 float4 per row
        int k4 = idx & 15;
        int lab = __ldg(&label[m0 + m]);
        reinterpret_cast<float4*>(s_emb[m])[k4] =
            __ldg(reinterpret_cast<const float4*>(table + (size_t)lab * H_SZ) + k4);
    }
    __syncthreads();

    // W row for this thread's column, in registers (16 float4 = 64 floats)
    float4 w[16];
    float bn = 0.0f;
    if (valid) {
        const float4* wp = reinterpret_cast<const float4*>(W + (size_t)n * H_SZ);
        #pragma unroll
        for (int k = 0; k < 16; k++) w[k] = wp[k];
        bn = __ldg(&b[n]);
    } else {
        #pragma unroll
        for (int k = 0; k < 16; k++) w[k] = make_float4(0.f, 0.f, 0.f, 0.f);
    }

    for (int m = 0; m < BM; m++) {
        float ex = 0.0f;
        if (valid) {
            const float4* e = reinterpret_cast<const float4*>(s_emb[m]);
            float acc = bn;
            #pragma unroll
            for (int k = 0; k < 16; k++) {
                float4 ev = e[k];
                acc = fmaf(ev.x, w[k].x, acc);
                acc = fmaf(ev.y, w[k].y, acc);
                acc = fmaf(ev.z, w[k].z, acc);
                acc = fmaf(ev.w, w[k].w, acc);
            }
            float sig = __fdividef(1.0f, 1.0f + __expf(-acc));
            out[(size_t)(m0 + m) * L_SZ + n] = sig;
            ex = __expf(sig);
        }
        // warp reduction (deterministic within warp)
        #pragma unroll
        for (int off = 16; off > 0; off >>= 1)
            ex += __shfl_down_sync(0xffffffffu, ex, off);
        if ((threadIdx.x & 31) == 0) s_warp[m][wid] = ex;
    }
    __syncthreads();

    // Fixed-order block reduction of the 8 warp partials per row
    if (threadIdx.x < BM) {
        int m = threadIdx.x;
        float s = 0.0f;
        #pragma unroll
        for (int w8 = 0; w8 < 8; w8++) s += s_warp[m][w8];
        g_partial[(size_t)(m0 + m) * GX + blockIdx.x] = s;
    }
}

// ---------------------------------------------------------------------------
// Kernel 3: deterministic row-sum reduction (one thread per row).
// ---------------------------------------------------------------------------
__global__ void rowsum_kernel() {
    int i = blockIdx.x * blockDim.x + threadIdx.x;
    if (i < B_SZ) {
        const float* p = &g_partial[(size_t)i * GX];
        float s = 0.0f;
        for (int j = 0; j < GX; j++) s += p[j];
        g_rowsum[i] = s;
    }
}

// ---------------------------------------------------------------------------
// Kernel 4: loss = mean(log(rowsum_i) - logits[i, label[i]]).
// Single block, fixed-order tree reduction.
// ---------------------------------------------------------------------------
__global__ void loss_kernel(const int* __restrict__ label,
                            const float* __restrict__ logits,
                            float* __restrict__ out_loss) {
    __shared__ float red[256];
    float s = 0.0f;
    for (int i = threadIdx.x; i < B_SZ; i += 256) {
        float lg = logits[(size_t)i * L_SZ + label[i]];
        s += logf(g_rowsum[i]) - lg;
    }
    red[threadIdx.x] = s;
    __syncthreads();
    for (int off = 128; off > 0; off >>= 1) {
        if (threadIdx.x < off) red[threadIdx.x] += red[threadIdx.x + off];
        __syncthreads();
    }
    if (threadIdx.x == 0) out_loss[0] = red[0] / (float)B_SZ;
}

// ---------------------------------------------------------------------------
extern "C" void kernel_launch(void* const* d_in, const int* in_sizes, int n_in,
                              void* d_out, int out_size) {
    const int*   label = (const int*)d_in[0];
    const float* table = (const float*)d_in[1];
    const float* W     = (const float*)d_in[2];
    const float* b     = (const float*)d_in[3];
    float* out = (float*)d_out;

    // Output layout: [logits (B*L) | loss (1) | return_embed (B*H)]
    float* out_logits = out;
    float* out_loss   = out + (size_t)B_SZ * L_SZ;
    float* out_embed  = out + (size_t)B_SZ * L_SZ + 1;

    prep_kernel<<<(B_SZ + 255) / 256, 256>>>(label, table, out_embed);

    dim3 grid(GX, GY);
    logits_kernel<<<grid, BN>>>(label, table, W, b, out_logits);

    rowsum_kernel<<<(B_SZ + 255) / 256, 256>>>();

    loss_kernel<<<1, 256>>>(label, out_logits, out_loss);
}